// round 3
// baseline (speedup 1.0000x reference)
#include <cuda_runtime.h>
#include <stdint.h>

// Complex linear folded into one real GEMM (legacy mma.sync tf32 path;
// tcgen05 is unreachable: harness compiles via compute_103 (no 'a')).
//   X = [x_re | x_im] (N x 1024), W = [[Re, -Im],[Im, Re]] (1024 x 1024)
//   out[n, 0:512] -> out_re, out[n, 512:1024] -> out_im  => (2, N, 512)
//
// W is stored k-permuted (per 16-chunk: quad t = {t, t+4, t+8, t+12}) so B
// fragments load as single LDS.128. A fragments load via ldmatrix.x4.b16.

#define M_ROWS 100000
#define KDIM   1024
#define NDIM   1024

#define BM 128
#define BN 128
#define BK 32
#define TILE_BYTES  (BM * BK * 4)        // 16384 per tile
#define STAGE_BYTES (2 * TILE_BYTES)     // A + B
#define SMEM_TOTAL  (2 * STAGE_BYTES)    // 2 stages = 64 KB

// Pre-built combined weight matrix, tf32-rounded, k-permuted. 4 MB static.
__device__ float g_W[NDIM * KDIM];

__device__ __forceinline__ uint32_t f2tf32(float f) {
    uint32_t r;
    asm("cvt.rna.tf32.f32 %0, %1;" : "=r"(r) : "f"(f));
    return r;
}

__global__ void build_W_kernel(const float* __restrict__ Re, const float* __restrict__ Im) {
    int idx = blockIdx.x * blockDim.x + threadIdx.x;   // 1M threads exactly
    int o    = idx >> 10;
    int knew = idx & 1023;
    // invert per-16-chunk permutation: new = 16c + 4t + j  =>  k = 16c + 4j + t
    int pos  = knew & 15;
    int k    = (knew & ~15) + (pos & 3) * 4 + (pos >> 2);
    float v;
    if (o < 512) v = (k < 512) ? Re[o * 512 + k] : -Im[o * 512 + (k - 512)];
    else         v = (k < 512) ? Im[(o - 512) * 512 + k] : Re[(o - 512) * 512 + (k - 512)];
    g_W[idx] = __uint_as_float(f2tf32(v));
}

__device__ __forceinline__ uint32_t smem_u32(const void* p) {
    uint32_t a;
    asm("{ .reg .u64 t; cvta.to.shared.u64 t, %1; cvt.u32.u64 %0, t; }" : "=r"(a) : "l"(p));
    return a;
}

__device__ __forceinline__ void cp_async16(uint32_t saddr, const void* gptr) {
    asm volatile("cp.async.cg.shared.global [%0], [%1], 16;\n" :: "r"(saddr), "l"(gptr));
}

__device__ __forceinline__ void ldsm_x4(uint32_t* r, uint32_t saddr) {
    asm volatile("ldmatrix.sync.aligned.m8n8.x4.shared.b16 {%0,%1,%2,%3}, [%4];"
                 : "=r"(r[0]), "=r"(r[1]), "=r"(r[2]), "=r"(r[3]) : "r"(saddr));
}

__device__ __forceinline__ void mma_tf32(float* c, uint32_t a0, uint32_t a1,
                                         uint32_t a2, uint32_t a3,
                                         uint32_t b0, uint32_t b1) {
    asm volatile(
        "mma.sync.aligned.m16n8k8.row.col.f32.tf32.tf32.f32 "
        "{%0,%1,%2,%3}, {%4,%5,%6,%7}, {%8,%9}, {%0,%1,%2,%3};\n"
        : "+f"(c[0]), "+f"(c[1]), "+f"(c[2]), "+f"(c[3])
        : "r"(a0), "r"(a1), "r"(a2), "r"(a3), "r"(b0), "r"(b1));
}

__global__ void __launch_bounds__(256, 2)
cplx_gemm_kernel(const float* __restrict__ xre, const float* __restrict__ xim,
                 float* __restrict__ out)
{
    extern __shared__ char smem[];
    const uint32_t sbase = smem_u32(smem);

    const int n_tile = blockIdx.x;   // 0..7
    const int m_tile = blockIdx.y;   // 0..781
    const int tid  = threadIdx.x;
    const int lane = tid & 31;
    const int warp = tid >> 5;
    const int wm0 = (warp & 3) * 32;   // warp tile: 32 (M) x 64 (N)
    const int wn0 = (warp >> 2) * 64;
    const int g = lane >> 2;
    const int t = lane & 3;

    // ldmatrix per-lane row/seg-half (fixed across mi/ks)
    const int a_lrow  = (lane & 7) + ((lane >> 4) << 3);  // 0..15 within 16-row block
    const int a_jhalf = (lane >> 3) & 1;                  // 0: k..k+3, 1: k+4..k+7

    float acc[2][8][4];
#pragma unroll
    for (int mi = 0; mi < 2; mi++)
#pragma unroll
        for (int ni = 0; ni < 8; ni++)
#pragma unroll
            for (int r = 0; r < 4; r++) acc[mi][ni][r] = 0.0f;

    const int NT = KDIM / BK;  // 32

    // ---- loader: cp.async into swizzled row-major (128B rows) tiles ----
    auto issue = [&](int kt, int buf) {
        const int k0 = kt * BK;
        const float* abase = (k0 < 512) ? (xre + k0) : (xim + (k0 - 512));
        const float* wbase = g_W + (size_t)(n_tile * BN) * KDIM + k0;
        const uint32_t a_s = sbase + buf * STAGE_BYTES;
        const uint32_t b_s = a_s + TILE_BYTES;
#pragma unroll
        for (int i = 0; i < 4; i++) {
            int idx = tid + i * 256;       // 0..1023
            int row = idx >> 3;            // 0..127
            int j   = idx & 7;             // 16B segment within row
            // A tile: seg = j ^ (row&7)
            int grow = m_tile * BM + row;
            if (grow >= M_ROWS) grow = M_ROWS - 1;   // clamp (rows never stored)
            cp_async16(a_s + row * 128 + ((j ^ (row & 7)) << 4),
                       abase + (size_t)grow * 512 + j * 4);
            // B tile: seg = j ^ ((row&1)<<2)
            cp_async16(b_s + row * 128 + ((j ^ ((row & 1) << 2)) << 4),
                       wbase + (size_t)row * KDIM + j * 4);
        }
        asm volatile("cp.async.commit_group;\n" ::: "memory");
    };

    // ---- compute one k-tile ----
    auto compute = [&](int buf) {
        const uint32_t a_s = sbase + buf * STAGE_BYTES;
        const uint32_t b_s = a_s + TILE_BYTES;
#pragma unroll
        for (int c = 0; c < 2; c++) {          // two 16-k chunks
            // A fragments for ks = 2c, 2c+1 via ldmatrix (order r0,r1,r2,r3 = a0,a2,a1,a3)
            uint32_t A[2][2][4];
#pragma unroll
            for (int mi = 0; mi < 2; mi++) {
                int row = wm0 + mi * 16 + a_lrow;
#pragma unroll
                for (int ksl = 0; ksl < 2; ksl++) {
                    int j = (2 * c + ksl) * 2 + a_jhalf;
                    ldsm_x4(A[mi][ksl], a_s + row * 128 + ((j ^ (row & 7)) << 4));
#pragma unroll
                    for (int q = 0; q < 4; q++)
                        A[mi][ksl][q] = f2tf32(__uint_as_float(A[mi][ksl][q]));
                }
            }
#pragma unroll
            for (int nh = 0; nh < 2; nh++) {   // n in halves to bound registers
                uint4 Bq[4];
#pragma unroll
                for (int nn = 0; nn < 4; nn++) {
                    int row = wn0 + (nh * 4 + nn) * 8 + g;
                    int qi  = c * 4 + t;       // quad = {t, t+4, t+8, t+12} (pre-permuted W)
                    Bq[nn] = *reinterpret_cast<const uint4*>(
                        (const char*)smem + (b_s - sbase) + row * 128
                        + ((qi ^ ((row & 1) << 2)) << 4));
                }
#pragma unroll
                for (int nn = 0; nn < 4; nn++) {
#pragma unroll
                    for (int mi = 0; mi < 2; mi++) {
                        // ks = 2c:   b = (Bq.x, Bq.y);  ks = 2c+1: b = (Bq.z, Bq.w)
                        mma_tf32(acc[mi][nh * 4 + nn],
                                 A[mi][0][0], A[mi][0][2], A[mi][0][1], A[mi][0][3],
                                 Bq[nn].x, Bq[nn].y);
                        mma_tf32(acc[mi][nh * 4 + nn],
                                 A[mi][1][0], A[mi][1][2], A[mi][1][1], A[mi][1][3],
                                 Bq[nn].z, Bq[nn].w);
                    }
                }
            }
        }
    };

    // ---- software-pipelined mainloop (2-stage) ----
    issue(0, 0);
    for (int kt = 0; kt < NT; kt++) {
        if (kt + 1 < NT) {
            issue(kt + 1, (kt + 1) & 1);
            asm volatile("cp.async.wait_group 1;\n" ::: "memory");
        } else {
            asm volatile("cp.async.wait_group 0;\n" ::: "memory");
        }
        __syncthreads();
        compute(kt & 1);
        __syncthreads();
    }

    // ---- epilogue: scatter into (2, N, 512) ----
#pragma unroll
    for (int mi = 0; mi < 2; mi++) {
        int row = m_tile * BM + wm0 + mi * 16 + g;
        if (row < M_ROWS) {   // M_ROWS % 16 == 0 -> row+8 also valid
#pragma unroll
            for (int ni = 0; ni < 8; ni++) {
                int co = n_tile * BN + wn0 + ni * 8 + (t << 1);
                int half = co >> 9;
                int col = co & 511;
                float* op = out + (size_t)half * ((size_t)M_ROWS * 512)
                                + (size_t)row * 512 + col;
                *reinterpret_cast<float2*>(op) = make_float2(acc[mi][ni][0], acc[mi][ni][1]);
                *reinterpret_cast<float2*>(op + 8 * 512) = make_float2(acc[mi][ni][2], acc[mi][ni][3]);
            }
        }
    }
}

extern "C" void kernel_launch(void* const* d_in, const int* in_sizes, int n_in,
                              void* d_out, int out_size)
{
    const float* xre = (const float*)d_in[0];
    const float* xim = (const float*)d_in[1];
    const float* Re  = (const float*)d_in[2];
    const float* Im  = (const float*)d_in[3];
    float* out = (float*)d_out;

    cudaFuncSetAttribute(cplx_gemm_kernel,
                         cudaFuncAttributeMaxDynamicSharedMemorySize, SMEM_TOTAL);

    build_W_kernel<<<(NDIM * KDIM) / 256, 256>>>(Re, Im);

    dim3 grid(NDIM / BN, (M_ROWS + BM - 1) / BM);  // (8, 782)
    cplx_gemm_kernel<<<grid, 256, SMEM_TOTAL>>>(xre, xim, out);
}

// round 5
// speedup vs baseline: 2.2279x; 2.2279x over previous
#include <cuda_runtime.h>
#include <cuda_fp16.h>
#include <stdint.h>

// Complex linear folded into one real fp16 GEMM (legacy mma.sync m16n8k16,
// fp32 accum; tcgen05 unreachable: harness targets plain sm_103).
//   X = [x_re | x_im] (N x 1024) fp16 (prepass), W = [[Re,-Im],[Im,Re]] fp16
//   out[n, 0:512] -> out_re, out[n, 512:1024] -> out_im  => (2, N, 512) fp32
// fp16 mantissa == tf32 mantissa (10 bits) -> same accuracy as passing tf32 runs.

#define M_ROWS 100000
#define KDIM   1024
#define NDIM   1024

#define BM 128
#define BN 128
#define BK 64
#define NT (KDIM / BK)                   // 16
#define TILE_BYTES  (BM * BK * 2)        // 16384 (fp16)
#define STAGE_BYTES (2 * TILE_BYTES)     // A + B = 32768
#define NSTAGE 3
#define SMEM_TOTAL (NSTAGE * STAGE_BYTES)  // 98304

// Static scratch (allocation-guard-safe): fp16 X (205MB) and combined W (2MB).
__device__ __half g_X[(size_t)M_ROWS * KDIM];
__device__ __half g_W[(size_t)NDIM * KDIM];

__global__ void build_X_kernel(const float* __restrict__ xre, const float* __restrict__ xim) {
    size_t id = (size_t)blockIdx.x * blockDim.x + threadIdx.x;  // 25.6M threads
    size_t e4 = id * 4;
    const size_t HALF = (size_t)M_ROWS * 512;
    bool is_im = e4 >= HALF;
    size_t off = is_im ? (e4 - HALF) : e4;
    const float4 v = *reinterpret_cast<const float4*>((is_im ? xim : xre) + off);
    size_t n = off >> 9;
    size_t k = off & 511;
    __half2* dst = reinterpret_cast<__half2*>(g_X + n * KDIM + (is_im ? 512 : 0) + k);
    dst[0] = __floats2half2_rn(v.x, v.y);
    dst[1] = __floats2half2_rn(v.z, v.w);
}

__global__ void build_W_kernel(const float* __restrict__ Re, const float* __restrict__ Im) {
    int idx = blockIdx.x * blockDim.x + threadIdx.x;   // 1M threads exactly
    int o = idx >> 10;
    int k = idx & 1023;
    float v;
    if (o < 512) v = (k < 512) ? Re[o * 512 + k] : -Im[o * 512 + (k - 512)];
    else         v = (k < 512) ? Im[(o - 512) * 512 + k] : Re[(o - 512) * 512 + (k - 512)];
    g_W[idx] = __float2half_rn(v);
}

__device__ __forceinline__ uint32_t smem_u32(const void* p) {
    uint32_t a;
    asm("{ .reg .u64 t; cvta.to.shared.u64 t, %1; cvt.u32.u64 %0, t; }" : "=r"(a) : "l"(p));
    return a;
}

__device__ __forceinline__ void cp_async16(uint32_t saddr, const void* gptr) {
    asm volatile("cp.async.cg.shared.global [%0], [%1], 16;\n" :: "r"(saddr), "l"(gptr));
}

__device__ __forceinline__ void ldsm_x4(uint32_t* r, uint32_t saddr) {
    asm volatile("ldmatrix.sync.aligned.m8n8.x4.shared.b16 {%0,%1,%2,%3}, [%4];"
                 : "=r"(r[0]), "=r"(r[1]), "=r"(r[2]), "=r"(r[3]) : "r"(saddr));
}

__device__ __forceinline__ void mma_f16(float* c, const uint32_t* a, uint32_t b0, uint32_t b1) {
    asm volatile(
        "mma.sync.aligned.m16n8k16.row.col.f32.f16.f16.f32 "
        "{%0,%1,%2,%3}, {%4,%5,%6,%7}, {%8,%9}, {%0,%1,%2,%3};\n"
        : "+f"(c[0]), "+f"(c[1]), "+f"(c[2]), "+f"(c[3])
        : "r"(a[0]), "r"(a[1]), "r"(a[2]), "r"(a[3]), "r"(b0), "r"(b1));
}

__global__ void __launch_bounds__(256, 2)
cplx_gemm_kernel(float* __restrict__ out)
{
    extern __shared__ char smem[];
    const uint32_t sbase = smem_u32(smem);

    const int n_tile = blockIdx.x;   // 0..7
    const int m_tile = blockIdx.y;   // 0..781
    const int tid  = threadIdx.x;
    const int lane = tid & 31;
    const int warp = tid >> 5;
    const int wm0 = (warp & 3) * 32;   // warp tile: 32 (M) x 64 (N)
    const int wn0 = (warp >> 2) * 64;
    const int g = lane >> 2;
    const int t = lane & 3;

    // per-lane ldmatrix row/seg components (rows of 128B = 8 x 16B segments)
    // A (x4): q = lane>>3: M0 rows0-7 kLo, M1 rows8-15 kLo, M2 rows0-7 kHi, M3 rows8-15 kHi
    const int a_row = (lane & 7) + (((lane >> 3) & 1) << 3);  // + wm0 + mi*16
    const int a_sh  = (lane >> 4) & 1;                        // seg = 2c + a_sh
    // B (x4): M0 nLo kLo, M1 nLo kHi, M2 nHi kLo, M3 nHi kHi
    const int b_row = (lane & 7) + (((lane >> 4) & 1) << 3);  // + wn0 + np*16
    const int b_sh  = (lane >> 3) & 1;                        // seg = 2c + b_sh

    float acc[2][8][4];
#pragma unroll
    for (int mi = 0; mi < 2; mi++)
#pragma unroll
        for (int ni = 0; ni < 8; ni++)
#pragma unroll
            for (int r = 0; r < 4; r++) acc[mi][ni][r] = 0.0f;

    // ---- loader: cp.async fp16 tiles, rows 128B, seg swizzle j^(row&7) ----
    auto issue = [&](int kt) {
        const int buf = kt % NSTAGE;
        const int k0 = kt * BK;
        const __half* abase = g_X + k0;
        const __half* wbase = g_W + (size_t)(n_tile * BN) * KDIM + k0;
        const uint32_t a_s = sbase + buf * STAGE_BYTES;
        const uint32_t b_s = a_s + TILE_BYTES;
#pragma unroll
        for (int i = 0; i < 4; i++) {
            int idx = tid + i * 256;       // 0..1023
            int row = idx >> 3;            // 0..127
            int j   = idx & 7;             // 16B segment
            int grow = m_tile * BM + row;
            if (grow >= M_ROWS) grow = M_ROWS - 1;   // clamp (rows never stored)
            cp_async16(a_s + row * 128 + ((j ^ (row & 7)) << 4),
                       abase + (size_t)grow * KDIM + j * 8);
            cp_async16(b_s + row * 128 + ((j ^ (row & 7)) << 4),
                       wbase + (size_t)row * KDIM + j * 8);
        }
        asm volatile("cp.async.commit_group;\n" ::: "memory");
    };

    // ---- compute one k-tile (4 chunks of k16) ----
    auto compute = [&](int buf) {
        const uint32_t a_s = sbase + buf * STAGE_BYTES;
        const uint32_t b_s = a_s + TILE_BYTES;
#pragma unroll
        for (int c = 0; c < 4; c++) {
            uint32_t A[2][4];
#pragma unroll
            for (int mi = 0; mi < 2; mi++) {
                int row = wm0 + mi * 16 + a_row;
                int seg = (2 * c + a_sh) ^ (row & 7);
                ldsm_x4(A[mi], a_s + row * 128 + (seg << 4));
            }
#pragma unroll
            for (int np = 0; np < 4; np++) {   // pairs of n-tiles
                uint32_t B[4];                 // b0(ni), b1(ni), b0(ni+1), b1(ni+1)
                int row = wn0 + np * 16 + b_row;
                int seg = (2 * c + b_sh) ^ (row & 7);
                ldsm_x4(B, b_s + row * 128 + (seg << 4));
#pragma unroll
                for (int sub = 0; sub < 2; sub++)
#pragma unroll
                    for (int mi = 0; mi < 2; mi++)
                        mma_f16(acc[mi][np * 2 + sub], A[mi], B[sub * 2], B[sub * 2 + 1]);
            }
        }
    };

    // ---- 3-stage pipeline, one barrier per iteration ----
    issue(0);
    issue(1);
    for (int kt = 0; kt < NT; kt++) {
        if (kt + 1 < NT) asm volatile("cp.async.wait_group 1;\n" ::: "memory");
        else             asm volatile("cp.async.wait_group 0;\n" ::: "memory");
        __syncthreads();            // stage kt resident; all warps done with buf (kt-1)%3
        if (kt + 2 < NT) issue(kt + 2);   // overwrites buf (kt-1)%3 — safe after barrier
        compute(kt % NSTAGE);
    }

    // ---- epilogue: scatter into (2, N, 512) ----
#pragma unroll
    for (int mi = 0; mi < 2; mi++) {
        int row = m_tile * BM + wm0 + mi * 16 + g;
        if (row < M_ROWS) {   // M_ROWS % 16 == 0 -> row+8 also valid
#pragma unroll
            for (int ni = 0; ni < 8; ni++) {
                int co = n_tile * BN + wn0 + ni * 8 + (t << 1);
                int half_ = co >> 9;
                int col = co & 511;
                float* op = out + (size_t)half_ * ((size_t)M_ROWS * 512)
                                + (size_t)row * 512 + col;
                *reinterpret_cast<float2*>(op) = make_float2(acc[mi][ni][0], acc[mi][ni][1]);
                *reinterpret_cast<float2*>(op + 8 * 512) = make_float2(acc[mi][ni][2], acc[mi][ni][3]);
            }
        }
    }
}

extern "C" void kernel_launch(void* const* d_in, const int* in_sizes, int n_in,
                              void* d_out, int out_size)
{
    const float* xre = (const float*)d_in[0];
    const float* xim = (const float*)d_in[1];
    const float* Re  = (const float*)d_in[2];
    const float* Im  = (const float*)d_in[3];
    float* out = (float*)d_out;

    cudaFuncSetAttribute(cplx_gemm_kernel,
                         cudaFuncAttributeMaxDynamicSharedMemorySize, SMEM_TOTAL);

    build_X_kernel<<<100000, 256>>>(xre, xim);           // 25.6M threads * 4 elems
    build_W_kernel<<<(NDIM * KDIM) / 256, 256>>>(Re, Im);

    dim3 grid(NDIM / BN, (M_ROWS + BM - 1) / BM);  // (8, 782)
    cplx_gemm_kernel<<<grid, 256, SMEM_TOTAL>>>(out);
}